// round 14
// baseline (speedup 1.0000x reference)
#include <cuda_runtime.h>
#include <cuda_fp16.h>

#define N_NODES  100000
#define N_EDGES  3200000
#define N_GRAPHS 256

static __device__ int   g_is64;
static __device__ int   g_ssrc[N_EDGES];      // src sorted by dst (CSR payload)
static __device__ int   g_erank[N_EDGES];     // rank of edge within its dst bucket
static __device__ int   g_cnt[N_NODES];
static __device__ int   g_rowptr[N_NODES + 1];
static __device__ float g_dinv[N_NODES];
static __device__ __align__(16) float   g_xs[(size_t)N_NODES * 8];    // x * dinv
static __device__ __align__(16) float   g_bufA[(size_t)N_NODES * 64];
static __device__ __align__(16) float   g_bufB[(size_t)N_NODES * 64];
static __device__ __align__(16) __half2 g_hbuf[(size_t)N_NODES * 32]; // agg-only features
static __device__ float g_psum[N_GRAPHS * 64];
static __device__ int   g_pcnt[N_GRAPHS];
static __device__ unsigned long long g_scanstate[128];  // lookback: flag<<32 | value

static constexpr int SCAN_CHUNK  = 1024;
static constexpr int SCAN_BLOCKS = (N_NODES + SCAN_CHUNK - 1) / SCAN_CHUNK;

// ------------------------------------------------------------- f32x2 helpers

typedef unsigned long long ull;

__device__ __forceinline__ ull pack2(float x, float y) {
    ull r; asm("mov.b64 %0, {%1,%2};" : "=l"(r) : "f"(x), "f"(y)); return r;
}
__device__ __forceinline__ float2 unpack2(ull v) {
    float x, y; asm("mov.b64 {%0,%1}, %2;" : "=f"(x), "=f"(y) : "l"(v));
    return make_float2(x, y);
}
__device__ __forceinline__ ull fma2(ull a, ull b, ull c) {
    ull d; asm("fma.rn.f32x2 %0, %1, %2, %3;" : "=l"(d) : "l"(a), "l"(b), "l"(c));
    return d;
}

// ---------------------------------------------------------------- utilities

__global__ void zero_detect_kernel(const int* __restrict__ ei32) {
    int i = blockIdx.x * blockDim.x + threadIdx.x;
    if (i < N_NODES)      g_cnt[i]  = 0;
    if (i < N_GRAPHS*64)  g_psum[i] = 0.f;
    if (i < N_GRAPHS)     g_pcnt[i] = 0;
    if (i < 128)          g_scanstate[i] = 0ULL;
    if (i == 0) {
        // int64 tensors have the high int32 word zero for values < 2^31
        int allz = 1;
        for (int k = 1; k < 256; k += 2) allz &= (ei32[k] == 0);
        g_is64 = allz;
    }
}

// Degree histogram over dst; ALSO records each edge's rank within its dst
// bucket (the atomicAdd return), so the later scatter needs no atomics.
__global__ void hist_rank_kernel(const void* __restrict__ eidx) {
    int e = blockIdx.x * blockDim.x + threadIdx.x;
    if (e >= N_EDGES) return;
    int d;
    if (g_is64) d = (int)((const long long*)eidx)[(size_t)N_EDGES + e];
    else        d = ((const int*)eidx)[N_EDGES + e];
    g_erank[e] = atomicAdd(&g_cnt[d], 1);
}

// --------------------------------------------- single-pass scan (+ finalize)
//
// Decoupled-lookback exclusive scan of g_cnt -> g_rowptr, fused with dinv
// computation and x pre-scaling (xs = x * dinv). All SCAN_BLOCKS (98) blocks
// are co-resident on 148 SMs, so the spin lookback cannot deadlock.
__global__ void scanfuse_kernel(const float* __restrict__ x) {
    __shared__ int s[SCAN_CHUNK];
    __shared__ int sprefix;
    int tid = threadIdx.x, b = blockIdx.x;
    int i = b * SCAN_CHUNK + tid;
    int v = (i < N_NODES) ? g_cnt[i] : 0;
    s[tid] = v;
    __syncthreads();
    for (int off = 1; off < SCAN_CHUNK; off <<= 1) {
        int t = (tid >= off) ? s[tid - off] : 0;
        __syncthreads();
        s[tid] += t;
        __syncthreads();
    }
    int total = s[SCAN_CHUNK - 1];
    if (tid == 0) {
        if (b == 0) {
            atomicExch(&g_scanstate[0], (2ULL << 32) | (unsigned)total);
            sprefix = 0;
        } else {
            atomicExch(&g_scanstate[b], (1ULL << 32) | (unsigned)total);
            long long prefix = 0;
            int j = b - 1;
            while (true) {
                ull w;
                do { w = atomicAdd(&g_scanstate[j], 0ULL); } while ((w >> 32) == 0ULL);
                prefix += (unsigned)w;
                if ((w >> 32) == 2ULL) break;
                j--;
            }
            atomicExch(&g_scanstate[b], (2ULL << 32) | (unsigned)(prefix + total));
            sprefix = (int)prefix;
        }
    }
    __syncthreads();
    int pre = sprefix;
    if (i < N_NODES) {
        g_rowptr[i] = pre + s[tid] - v;   // exclusive
        float dv = rsqrtf((float)v + 1.0f);
        g_dinv[i] = dv;
        const float4* xp = (const float4*)(x + (size_t)i * 8);
        float4 u = xp[0], v4 = xp[1];
        float4* op = (float4*)(g_xs + (size_t)i * 8);
        op[0] = make_float4(u.x * dv, u.y * dv, u.z * dv, u.w * dv);
        op[1] = make_float4(v4.x * dv, v4.y * dv, v4.z * dv, v4.w * dv);
    }
    if (i == N_NODES) g_rowptr[N_NODES] = N_EDGES;
}

// Atomic-free scatter into CSR: slot = rowptr[dst] + precomputed rank.
__global__ void fill_kernel(const void* __restrict__ eidx) {
    int e = blockIdx.x * blockDim.x + threadIdx.x;
    if (e >= N_EDGES) return;
    int s, d;
    if (g_is64) {
        const long long* p = (const long long*)eidx;
        s = (int)p[e];
        d = (int)p[(size_t)N_EDGES + e];
    } else {
        const int* p = (const int*)eidx;
        s = p[e];
        d = p[N_EDGES + e];
    }
    g_ssrc[g_rowptr[d] + g_erank[e]] = s;
}

// ------------------------------------------------- layer 1: fused agg + GEMM
//
// With h' = dinv*h pre-scaled, GCN aggregation is out_i = dinv_i*(h'_i + sum h'_j).
// One warp per node: gather-sum xs (8-d), butterfly-reduce (full sum in every
// lane), each lane computes 2 cols of the 8->64 GEMM + bias + relu + dinv
// pre-scale, stored as half2 (consumed only by the layer-2 aggregation).
__global__ void aggX_gemm1_kernel(const float* __restrict__ W1,
                                  const float* __restrict__ b1) {
    __shared__ float sW[8 * 64];
    __shared__ float sB[64];
    int tid = threadIdx.x;
    for (int i = tid; i < 512; i += 256) sW[i] = W1[i];
    if (tid < 64) sB[tid] = b1[tid];
    __syncthreads();

    int w = (blockIdx.x * blockDim.x + tid) >> 5;
    if (w >= N_NODES) return;
    int lane = tid & 31;
    int beg = g_rowptr[w], end = g_rowptr[w + 1];
    float a0=0,a1=0,a2=0,a3=0,a4=0,a5=0,a6=0,a7=0;
    for (int e = beg + lane; e < end; e += 32) {
        int s = g_ssrc[e];
        const float4* xp = (const float4*)(g_xs + (size_t)s * 8);
        float4 u = xp[0], v = xp[1];
        a0 += u.x; a1 += u.y; a2 += u.z; a3 += u.w;
        a4 += v.x; a5 += v.y; a6 += v.z; a7 += v.w;
    }
    #pragma unroll
    for (int off = 16; off; off >>= 1) {
        a0 += __shfl_xor_sync(0xffffffffu, a0, off);
        a1 += __shfl_xor_sync(0xffffffffu, a1, off);
        a2 += __shfl_xor_sync(0xffffffffu, a2, off);
        a3 += __shfl_xor_sync(0xffffffffu, a3, off);
        a4 += __shfl_xor_sync(0xffffffffu, a4, off);
        a5 += __shfl_xor_sync(0xffffffffu, a5, off);
        a6 += __shfl_xor_sync(0xffffffffu, a6, off);
        a7 += __shfl_xor_sync(0xffffffffu, a7, off);
    }
    float dv = g_dinv[w];
    const float4* xp = (const float4*)(g_xs + (size_t)w * 8);
    float4 u = xp[0], v = xp[1];
    float s[8];
    s[0]=dv*(a0+u.x); s[1]=dv*(a1+u.y); s[2]=dv*(a2+u.z); s[3]=dv*(a3+u.w);
    s[4]=dv*(a4+v.x); s[5]=dv*(a5+v.y); s[6]=dv*(a6+v.z); s[7]=dv*(a7+v.w);
    int c = lane * 2;
    float o0 = sB[c], o1 = sB[c + 1];
    #pragma unroll
    for (int k = 0; k < 8; k++) {
        float2 wv = *(const float2*)&sW[k * 64 + c];
        o0 = fmaf(s[k], wv.x, o0);
        o1 = fmaf(s[k], wv.y, o1);
    }
    o0 = fmaxf(o0, 0.f) * dv;
    o1 = fmaxf(o1, 0.f) * dv;
    g_hbuf[(size_t)w * 32 + lane] = __floats2half2_rn(o0, o1);
}

// ---------------------------------------------------------------- aggregation

// F=64 aggregation from the half2 feature buffer. One warp per dst node, lane
// owns one half2 column pair; fp32 accumulation; 8-way edge unroll for MLP.
// outSel: 0 -> g_bufA, 1 -> g_bufB (resolved in-kernel).
template <bool BIAS_RELU>
__global__ void agg64h_kernel(int outSel, const float* __restrict__ bias) {
    int w = (blockIdx.x * blockDim.x + threadIdx.x) >> 5;
    if (w >= N_NODES) return;
    int lane = threadIdx.x & 31;
    float* __restrict__ out = outSel ? g_bufB : g_bufA;
    const __half2* __restrict__ in = g_hbuf;
    int e = g_rowptr[w], end = g_rowptr[w + 1];
    float ax0=0, ay0=0, ax1=0, ay1=0, ax2=0, ay2=0, ax3=0, ay3=0;
    for (; e + 8 <= end; e += 8) {
        int s0 = g_ssrc[e+0], s1 = g_ssrc[e+1], s2 = g_ssrc[e+2], s3 = g_ssrc[e+3];
        int s4 = g_ssrc[e+4], s5 = g_ssrc[e+5], s6 = g_ssrc[e+6], s7 = g_ssrc[e+7];
        __half2 h0 = in[(size_t)s0*32 + lane];
        __half2 h1 = in[(size_t)s1*32 + lane];
        __half2 h2 = in[(size_t)s2*32 + lane];
        __half2 h3 = in[(size_t)s3*32 + lane];
        __half2 h4 = in[(size_t)s4*32 + lane];
        __half2 h5 = in[(size_t)s5*32 + lane];
        __half2 h6 = in[(size_t)s6*32 + lane];
        __half2 h7 = in[(size_t)s7*32 + lane];
        float2 f0 = __half22float2(h0), f1 = __half22float2(h1);
        float2 f2 = __half22float2(h2), f3 = __half22float2(h3);
        float2 f4 = __half22float2(h4), f5 = __half22float2(h5);
        float2 f6 = __half22float2(h6), f7 = __half22float2(h7);
        ax0 += f0.x; ay0 += f0.y;  ax1 += f1.x; ay1 += f1.y;
        ax2 += f2.x; ay2 += f2.y;  ax3 += f3.x; ay3 += f3.y;
        ax0 += f4.x; ay0 += f4.y;  ax1 += f5.x; ay1 += f5.y;
        ax2 += f6.x; ay2 += f6.y;  ax3 += f7.x; ay3 += f7.y;
    }
    for (; e < end; e++) {
        int s = g_ssrc[e];
        float2 f = __half22float2(in[(size_t)s*32 + lane]);
        ax0 += f.x; ay0 += f.y;
    }
    float dv = g_dinv[w];
    float2 sv = __half22float2(in[(size_t)w*32 + lane]);
    float ox = dv * ((ax0 + ax1) + (ax2 + ax3) + sv.x);
    float oy = dv * ((ay0 + ay1) + (ay2 + ay3) + sv.y);
    int c = lane * 2;
    if (BIAS_RELU) {
        ox = fmaxf(ox + bias[c],     0.f);
        oy = fmaxf(oy + bias[c + 1], 0.f);
    }
    *(float2*)(out + (size_t)w*64 + c) = make_float2(ox, oy);
}

// ------------------------------------------------------- fused GEMM2 + GEMM3
//
// h2 = relu(h1agg * W2 + b2)  [64 -> 128], kept in smem;
// h3 = (h2 * W3) * dinv       [128 -> 64], written as half2 to g_hbuf.
// One kernel: saves the 51MB x2 bufA round-trip and a launch.
// Block = 256 threads, 32 nodes per block. f32x2 FMAs throughout.
__global__ void gemm23_kernel(const float* __restrict__ W2,
                              const float* __restrict__ b2,
                              const float* __restrict__ W3) {
    constexpr int NPB = 32;
    constexpr int MSTR = 130;                 // sMid row stride (floats)
    extern __shared__ float smem[];
    float* sW2 = smem;                        // 64*128
    float* sW3 = sW2 + 64 * 128;              // 128*64
    float* sB2 = sW3 + 128 * 64;              // 128
    float* sH  = sB2 + 128;                   // 32*65
    float* sMid= sH  + NPB * 65;              // 32*130
    int tid = threadIdx.x;
    for (int i = tid; i < 64 * 128; i += 256) sW2[i] = W2[i];
    for (int i = tid; i < 128 * 64; i += 256) sW3[i] = W3[i];
    if (tid < 128) sB2[tid] = b2[tid];
    int base = blockIdx.x * NPB;
    for (int i = tid; i < NPB * 64; i += 256) {
        int nd = i / 64, k = i % 64;
        int node = base + nd;
        sH[nd * 65 + k] = (node < N_NODES) ? g_bufB[(size_t)node * 64 + k] : 0.f;
    }
    __syncthreads();

    // ---- phase 1: 64 -> 128, relu, to sMid. CPT=8 -> TPN=16, NL=16, MPT=2.
    {
        int cg = tid % 16, nl = tid / 16;
        ull acc[2][4];
        #pragma unroll
        for (int j = 0; j < 2; j++)
            #pragma unroll
            for (int q = 0; q < 4; q++)
                acc[j][q] = pack2(sB2[cg*8 + 2*q], sB2[cg*8 + 2*q + 1]);
        #pragma unroll 4
        for (int k = 0; k < 64; k++) {
            const ull* wp = reinterpret_cast<const ull*>(sW2 + k * 128 + cg * 8);
            ull wv[4];
            #pragma unroll
            for (int q = 0; q < 4; q++) wv[q] = wp[q];
            #pragma unroll
            for (int j = 0; j < 2; j++) {
                float a = sH[(nl * 2 + j) * 65 + k];
                ull ap = pack2(a, a);
                #pragma unroll
                for (int q = 0; q < 4; q++)
                    acc[j][q] = fma2(ap, wv[q], acc[j][q]);
            }
        }
        #pragma unroll
        for (int j = 0; j < 2; j++) {
            float* mp = sMid + (nl * 2 + j) * MSTR + cg * 8;
            #pragma unroll
            for (int q = 0; q < 4; q++) {
                float2 v = unpack2(acc[j][q]);
                v.x = fmaxf(v.x, 0.f); v.y = fmaxf(v.y, 0.f);
                *(float2*)(mp + 2*q) = v;
            }
        }
    }
    __syncthreads();

    // ---- phase 2: 128 -> 64, *dinv, half2 out. CPT=8 -> TPN=8, NL=32, MPT=1.
    {
        int cg = tid % 8, nl = tid / 8;
        int node = base + nl;
        ull acc[4] = {0, 0, 0, 0};
        const float* mrow = sMid + nl * MSTR;
        #pragma unroll 4
        for (int k = 0; k < 128; k++) {
            const ull* wp = reinterpret_cast<const ull*>(sW3 + k * 64 + cg * 8);
            float a = mrow[k];
            ull ap = pack2(a, a);
            #pragma unroll
            for (int q = 0; q < 4; q++)
                acc[q] = fma2(ap, wp[q], acc[q]);
        }
        if (node < N_NODES) {
            float dv = g_dinv[node];
            #pragma unroll
            for (int q = 0; q < 4; q++) {
                float2 v = unpack2(acc[q]);
                g_hbuf[(size_t)node * 32 + cg * 4 + q] =
                    __floats2half2_rn(v.x * dv, v.y * dv);
            }
        }
    }
}

// ---------------------------------------------------------------- pooling + MLP

__global__ void pool_kernel(const void* __restrict__ batch) {
    int w = (blockIdx.x * blockDim.x + threadIdx.x) >> 5;
    int lane = threadIdx.x & 31;
    const int NPW = 64;
    int start = w * NPW;
    if (start >= N_NODES) return;
    int end = min(start + NPW, N_NODES);
    int is64 = g_is64;
    int c = lane * 2;
    float ax = 0.f, ay = 0.f;
    int curg = -1, cnt = 0;
    for (int i = start; i < end; i++) {
        int g = is64 ? (int)((const long long*)batch)[i] : ((const int*)batch)[i];
        if (g != curg) {
            if (curg >= 0) {
                atomicAdd(&g_psum[curg * 64 + c],     ax);
                atomicAdd(&g_psum[curg * 64 + c + 1], ay);
                if (lane == 0) atomicAdd(&g_pcnt[curg], cnt);
            }
            curg = g; ax = 0.f; ay = 0.f; cnt = 0;
        }
        float2 v = *(const float2*)(g_bufA + (size_t)i * 64 + c);
        ax += v.x; ay += v.y; cnt++;
    }
    if (curg >= 0) {
        atomicAdd(&g_psum[curg * 64 + c],     ax);
        atomicAdd(&g_psum[curg * 64 + c + 1], ay);
        if (lane == 0) atomicAdd(&g_pcnt[curg], cnt);
    }
}

__global__ void mlp_kernel(const float* __restrict__ Wl1, const float* __restrict__ bl1,
                           const float* __restrict__ Wl2, const float* __restrict__ bl2,
                           float* __restrict__ out) {
    __shared__ float sW1[64 * 32];
    __shared__ float sb1[32];
    __shared__ float sW2[32];
    __shared__ float sb2;
    int tid = threadIdx.x;
    for (int i = tid; i < 64 * 32; i += 256) sW1[i] = Wl1[i];
    if (tid < 32) { sb1[tid] = bl1[tid]; sW2[tid] = Wl2[tid]; }
    if (tid == 0) sb2 = bl2[0];
    __syncthreads();
    float inv = 1.0f / fmaxf((float)g_pcnt[tid], 1.0f);
    float hid[32];
    #pragma unroll
    for (int cc = 0; cc < 32; cc++) hid[cc] = sb1[cc];
    for (int k = 0; k < 64; k++) {
        float a = g_psum[tid * 64 + k] * inv;
        #pragma unroll
        for (int cc = 0; cc < 32; cc++) hid[cc] = fmaf(a, sW1[k * 32 + cc], hid[cc]);
    }
    float o = sb2;
    #pragma unroll
    for (int cc = 0; cc < 32; cc++) o = fmaf(fmaxf(hid[cc], 0.f), sW2[cc], o);
    out[tid] = o;
}

// ---------------------------------------------------------------- launch

extern "C" void kernel_launch(void* const* d_in, const int* in_sizes, int n_in,
                              void* d_out, int out_size) {
    const float* x    = (const float*)d_in[0];
    const void*  eidx = d_in[1];
    const void*  batch= d_in[2];
    const float* W1   = (const float*)d_in[3];
    const float* b1   = (const float*)d_in[4];
    const float* W2   = (const float*)d_in[5];
    const float* b2   = (const float*)d_in[6];
    const float* W3   = (const float*)d_in[7];
    const float* b3   = (const float*)d_in[8];
    const float* Wl1  = (const float*)d_in[9];
    const float* bl1  = (const float*)d_in[10];
    const float* Wl2  = (const float*)d_in[11];
    const float* bl2  = (const float*)d_in[12];
    float* out = (float*)d_out;

    // gemm23 smem: W2 + W3 + b2 + sH + sMid (floats)
    constexpr int SM23 = (64*128 + 128*64 + 128 + 32*65 + 32*130) * 4;
    cudaFuncSetAttribute(gemm23_kernel,
                         cudaFuncAttributeMaxDynamicSharedMemorySize, SM23);

    const int warpGrid = (N_NODES * 32 + 255) / 256;

    zero_detect_kernel<<<(N_NODES + 255) / 256, 256>>>((const int*)eidx);
    hist_rank_kernel  <<<(N_EDGES + 255) / 256, 256>>>(eidx);
    scanfuse_kernel   <<<SCAN_BLOCKS, SCAN_CHUNK>>>(x);
    fill_kernel       <<<(N_EDGES + 255) / 256, 256>>>(eidx);

    // Layer 1 (fused): agg xs (8-d) + GEMM 8->64 + b1 + relu + dinv -> hbuf (fp16)
    aggX_gemm1_kernel<<<warpGrid, 256>>>(W1, b1);
    // Layer 2 agg: hbuf -> bufB (fp32, 64-d)
    agg64h_kernel<false><<<warpGrid, 256>>>(1, nullptr);
    // Fused GEMM2+GEMM3: bufB -> (relu 128-d in smem) -> *dinv -> hbuf (fp16)
    gemm23_kernel<<<(N_NODES + 31) / 32, 256, SM23>>>(W2, b2, W3);
    // Layer 3 agg: hbuf -> bufA (+b3, relu)
    agg64h_kernel<true><<<warpGrid, 256>>>(0, b3);

    pool_kernel<<<(((N_NODES + 63) / 64) * 32 + 255) / 256, 256>>>(batch);
    mlp_kernel<<<1, 256>>>(Wl1, bl1, Wl2, bl2, out);
}

// round 16
// speedup vs baseline: 1.0689x; 1.0689x over previous
#include <cuda_runtime.h>
#include <cuda_fp16.h>

#define N_NODES  100000
#define N_EDGES  3200000
#define N_GRAPHS 256

static __device__ int   g_is64;
static __device__ int   g_ssrc[N_EDGES];      // src sorted by dst (CSR payload)
static __device__ int   g_erank[N_EDGES];     // rank of edge within its dst bucket
static __device__ int   g_cnt[N_NODES];
static __device__ int   g_rowptr[N_NODES + 1];
static __device__ float g_dinv[N_NODES];
static __device__ __align__(16) float   g_xs[(size_t)N_NODES * 8];    // x * dinv
static __device__ __align__(16) float   g_bufA[(size_t)N_NODES * 64];
static __device__ __align__(16) float   g_bufB[(size_t)N_NODES * 64];
static __device__ __align__(16) __half2 g_hbuf[(size_t)N_NODES * 32]; // agg-only features
static __device__ float g_psum[N_GRAPHS * 64];
static __device__ int   g_pcnt[N_GRAPHS];
static __device__ unsigned long long g_scanstate[128];  // lookback: flag<<32 | value

static constexpr int SCAN_CHUNK  = 1024;
static constexpr int SCAN_BLOCKS = (N_NODES + SCAN_CHUNK - 1) / SCAN_CHUNK;

// ------------------------------------------------------------- f32x2 helpers

typedef unsigned long long ull;

__device__ __forceinline__ ull pack2(float x, float y) {
    ull r; asm("mov.b64 %0, {%1,%2};" : "=l"(r) : "f"(x), "f"(y)); return r;
}
__device__ __forceinline__ float2 unpack2(ull v) {
    float x, y; asm("mov.b64 {%0,%1}, %2;" : "=f"(x), "=f"(y) : "l"(v));
    return make_float2(x, y);
}
__device__ __forceinline__ ull fma2(ull a, ull b, ull c) {
    ull d; asm("fma.rn.f32x2 %0, %1, %2, %3;" : "=l"(d) : "l"(a), "l"(b), "l"(c));
    return d;
}

// ---------------------------------------------------------------- utilities

__global__ void zero_detect_kernel(const int* __restrict__ ei32) {
    int i = blockIdx.x * blockDim.x + threadIdx.x;
    if (i < N_NODES)      g_cnt[i]  = 0;
    if (i < N_GRAPHS*64)  g_psum[i] = 0.f;
    if (i < N_GRAPHS)     g_pcnt[i] = 0;
    if (i < 128)          g_scanstate[i] = 0ULL;
    if (i == 0) {
        // int64 tensors have the high int32 word zero for values < 2^31
        int allz = 1;
        for (int k = 1; k < 256; k += 2) allz &= (ei32[k] == 0);
        g_is64 = allz;
    }
}

// Degree histogram over dst; ALSO records each edge's rank within its dst
// bucket (the atomicAdd return), so the later scatter needs no atomics.
__global__ void hist_rank_kernel(const void* __restrict__ eidx) {
    int e = blockIdx.x * blockDim.x + threadIdx.x;
    if (e >= N_EDGES) return;
    int d;
    if (g_is64) d = (int)((const long long*)eidx)[(size_t)N_EDGES + e];
    else        d = ((const int*)eidx)[N_EDGES + e];
    g_erank[e] = atomicAdd(&g_cnt[d], 1);
}

// --------------------------------------------- single-pass scan (+ finalize)
//
// Decoupled-lookback exclusive scan of g_cnt -> g_rowptr, fused with dinv
// computation and x pre-scaling (xs = x * dinv). All SCAN_BLOCKS (98) blocks
// are co-resident on 148 SMs, so the spin lookback cannot deadlock.
__global__ void scanfuse_kernel(const float* __restrict__ x) {
    __shared__ int s[SCAN_CHUNK];
    __shared__ int sprefix;
    int tid = threadIdx.x, b = blockIdx.x;
    int i = b * SCAN_CHUNK + tid;
    int v = (i < N_NODES) ? g_cnt[i] : 0;
    s[tid] = v;
    __syncthreads();
    for (int off = 1; off < SCAN_CHUNK; off <<= 1) {
        int t = (tid >= off) ? s[tid - off] : 0;
        __syncthreads();
        s[tid] += t;
        __syncthreads();
    }
    int total = s[SCAN_CHUNK - 1];
    if (tid == 0) {
        if (b == 0) {
            atomicExch(&g_scanstate[0], (2ULL << 32) | (unsigned)total);
            sprefix = 0;
        } else {
            atomicExch(&g_scanstate[b], (1ULL << 32) | (unsigned)total);
            long long prefix = 0;
            int j = b - 1;
            while (true) {
                ull w;
                do { w = atomicAdd(&g_scanstate[j], 0ULL); } while ((w >> 32) == 0ULL);
                prefix += (unsigned)w;
                if ((w >> 32) == 2ULL) break;
                j--;
            }
            atomicExch(&g_scanstate[b], (2ULL << 32) | (unsigned)(prefix + total));
            sprefix = (int)prefix;
        }
    }
    __syncthreads();
    int pre = sprefix;
    if (i < N_NODES) {
        g_rowptr[i] = pre + s[tid] - v;   // exclusive
        float dv = rsqrtf((float)v + 1.0f);
        g_dinv[i] = dv;
        const float4* xp = (const float4*)(x + (size_t)i * 8);
        float4 u = xp[0], v4 = xp[1];
        float4* op = (float4*)(g_xs + (size_t)i * 8);
        op[0] = make_float4(u.x * dv, u.y * dv, u.z * dv, u.w * dv);
        op[1] = make_float4(v4.x * dv, v4.y * dv, v4.z * dv, v4.w * dv);
    }
    if (i == N_NODES) g_rowptr[N_NODES] = N_EDGES;
}

// Atomic-free scatter into CSR: slot = rowptr[dst] + precomputed rank.
__global__ void fill_kernel(const void* __restrict__ eidx) {
    int e = blockIdx.x * blockDim.x + threadIdx.x;
    if (e >= N_EDGES) return;
    int s, d;
    if (g_is64) {
        const long long* p = (const long long*)eidx;
        s = (int)p[e];
        d = (int)p[(size_t)N_EDGES + e];
    } else {
        const int* p = (const int*)eidx;
        s = p[e];
        d = p[N_EDGES + e];
    }
    g_ssrc[g_rowptr[d] + g_erank[e]] = s;
}

// ------------------------------------------------- layer 1: fused agg + GEMM
//
// With h' = dinv*h pre-scaled, GCN aggregation is out_i = dinv_i*(h'_i + sum h'_j).
// One warp per node: gather-sum xs (8-d), butterfly-reduce (full sum in every
// lane), each lane computes 2 cols of the 8->64 GEMM + bias + relu + dinv
// pre-scale, stored as half2 (consumed only by the layer-2 aggregation).
__global__ void aggX_gemm1_kernel(const float* __restrict__ W1,
                                  const float* __restrict__ b1) {
    __shared__ float sW[8 * 64];
    __shared__ float sB[64];
    int tid = threadIdx.x;
    for (int i = tid; i < 512; i += 256) sW[i] = W1[i];
    if (tid < 64) sB[tid] = b1[tid];
    __syncthreads();

    int w = (blockIdx.x * blockDim.x + tid) >> 5;
    if (w >= N_NODES) return;
    int lane = tid & 31;
    int beg = g_rowptr[w], end = g_rowptr[w + 1];
    float a0=0,a1=0,a2=0,a3=0,a4=0,a5=0,a6=0,a7=0;
    for (int e = beg + lane; e < end; e += 32) {
        int s = g_ssrc[e];
        const float4* xp = (const float4*)(g_xs + (size_t)s * 8);
        float4 u = xp[0], v = xp[1];
        a0 += u.x; a1 += u.y; a2 += u.z; a3 += u.w;
        a4 += v.x; a5 += v.y; a6 += v.z; a7 += v.w;
    }
    #pragma unroll
    for (int off = 16; off; off >>= 1) {
        a0 += __shfl_xor_sync(0xffffffffu, a0, off);
        a1 += __shfl_xor_sync(0xffffffffu, a1, off);
        a2 += __shfl_xor_sync(0xffffffffu, a2, off);
        a3 += __shfl_xor_sync(0xffffffffu, a3, off);
        a4 += __shfl_xor_sync(0xffffffffu, a4, off);
        a5 += __shfl_xor_sync(0xffffffffu, a5, off);
        a6 += __shfl_xor_sync(0xffffffffu, a6, off);
        a7 += __shfl_xor_sync(0xffffffffu, a7, off);
    }
    float dv = g_dinv[w];
    const float4* xp = (const float4*)(g_xs + (size_t)w * 8);
    float4 u = xp[0], v = xp[1];
    float s[8];
    s[0]=dv*(a0+u.x); s[1]=dv*(a1+u.y); s[2]=dv*(a2+u.z); s[3]=dv*(a3+u.w);
    s[4]=dv*(a4+v.x); s[5]=dv*(a5+v.y); s[6]=dv*(a6+v.z); s[7]=dv*(a7+v.w);
    int c = lane * 2;
    float o0 = sB[c], o1 = sB[c + 1];
    #pragma unroll
    for (int k = 0; k < 8; k++) {
        float2 wv = *(const float2*)&sW[k * 64 + c];
        o0 = fmaf(s[k], wv.x, o0);
        o1 = fmaf(s[k], wv.y, o1);
    }
    o0 = fmaxf(o0, 0.f) * dv;
    o1 = fmaxf(o1, 0.f) * dv;
    g_hbuf[(size_t)w * 32 + lane] = __floats2half2_rn(o0, o1);
}

// ---------------------------------------------------------------- aggregation

// F=64 aggregation from the half2 feature buffer. One warp per dst node, lane
// owns one half2 column pair; fp32 accumulation; 8-way edge unroll for MLP.
// outSel: 0 -> g_bufA, 1 -> g_bufB (resolved in-kernel).
template <bool BIAS_RELU>
__global__ void agg64h_kernel(int outSel, const float* __restrict__ bias) {
    int w = (blockIdx.x * blockDim.x + threadIdx.x) >> 5;
    if (w >= N_NODES) return;
    int lane = threadIdx.x & 31;
    float* __restrict__ out = outSel ? g_bufB : g_bufA;
    const __half2* __restrict__ in = g_hbuf;
    int e = g_rowptr[w], end = g_rowptr[w + 1];
    float ax0=0, ay0=0, ax1=0, ay1=0, ax2=0, ay2=0, ax3=0, ay3=0;
    for (; e + 8 <= end; e += 8) {
        int s0 = g_ssrc[e+0], s1 = g_ssrc[e+1], s2 = g_ssrc[e+2], s3 = g_ssrc[e+3];
        int s4 = g_ssrc[e+4], s5 = g_ssrc[e+5], s6 = g_ssrc[e+6], s7 = g_ssrc[e+7];
        __half2 h0 = in[(size_t)s0*32 + lane];
        __half2 h1 = in[(size_t)s1*32 + lane];
        __half2 h2 = in[(size_t)s2*32 + lane];
        __half2 h3 = in[(size_t)s3*32 + lane];
        __half2 h4 = in[(size_t)s4*32 + lane];
        __half2 h5 = in[(size_t)s5*32 + lane];
        __half2 h6 = in[(size_t)s6*32 + lane];
        __half2 h7 = in[(size_t)s7*32 + lane];
        float2 f0 = __half22float2(h0), f1 = __half22float2(h1);
        float2 f2 = __half22float2(h2), f3 = __half22float2(h3);
        float2 f4 = __half22float2(h4), f5 = __half22float2(h5);
        float2 f6 = __half22float2(h6), f7 = __half22float2(h7);
        ax0 += f0.x; ay0 += f0.y;  ax1 += f1.x; ay1 += f1.y;
        ax2 += f2.x; ay2 += f2.y;  ax3 += f3.x; ay3 += f3.y;
        ax0 += f4.x; ay0 += f4.y;  ax1 += f5.x; ay1 += f5.y;
        ax2 += f6.x; ay2 += f6.y;  ax3 += f7.x; ay3 += f7.y;
    }
    for (; e < end; e++) {
        int s = g_ssrc[e];
        float2 f = __half22float2(in[(size_t)s*32 + lane]);
        ax0 += f.x; ay0 += f.y;
    }
    float dv = g_dinv[w];
    float2 sv = __half22float2(in[(size_t)w*32 + lane]);
    float ox = dv * ((ax0 + ax1) + (ax2 + ax3) + sv.x);
    float oy = dv * ((ay0 + ay1) + (ay2 + ay3) + sv.y);
    int c = lane * 2;
    if (BIAS_RELU) {
        ox = fmaxf(ox + bias[c],     0.f);
        oy = fmaxf(oy + bias[c + 1], 0.f);
    }
    *(float2*)(out + (size_t)w*64 + c) = make_float2(ox, oy);
}

// ------------------------------------------------------- fused GEMM2 + GEMM3
//
// h2 = relu(h1agg * W2 + b2)  [64 -> 128], kept in smem;
// h3 = (h2 * W3) * dinv       [128 -> 64], written as half2 to g_hbuf.
// GRID-STRIDE: weights staged ONCE per block (128KB), then ~11 tiles of 32
// nodes each — weight traffic 296 x 128KB = 38MB instead of 400MB (the R14
// regression). Keeps the fusion win: no bufA round-trip.
__global__ void gemm23_kernel(const float* __restrict__ W2,
                              const float* __restrict__ b2,
                              const float* __restrict__ W3) {
    constexpr int NPB = 32;
    constexpr int MSTR = 130;                 // sMid row stride (floats)
    extern __shared__ float smem[];
    float* sW2 = smem;                        // 64*128
    float* sW3 = sW2 + 64 * 128;              // 128*64
    float* sB2 = sW3 + 128 * 64;              // 128
    float* sH  = sB2 + 128;                   // 32*65
    float* sMid= sH  + NPB * 65;              // 32*130
    int tid = threadIdx.x;
    for (int i = tid; i < 64 * 128; i += 256) sW2[i] = W2[i];
    for (int i = tid; i < 128 * 64; i += 256) sW3[i] = W3[i];
    if (tid < 128) sB2[tid] = b2[tid];

    for (int base = blockIdx.x * NPB; base < N_NODES; base += gridDim.x * NPB) {
        __syncthreads();   // weights ready (1st iter) / previous tile done
        for (int i = tid; i < NPB * 64; i += 256) {
            int nd = i / 64, k = i % 64;
            int node = base + nd;
            sH[nd * 65 + k] = (node < N_NODES) ? g_bufB[(size_t)node * 64 + k] : 0.f;
        }
        __syncthreads();

        // ---- phase 1: 64 -> 128, relu, to sMid. TPN=16, NL=16, MPT=2.
        {
            int cg = tid % 16, nl = tid / 16;
            ull acc[2][4];
            #pragma unroll
            for (int j = 0; j < 2; j++)
                #pragma unroll
                for (int q = 0; q < 4; q++)
                    acc[j][q] = pack2(sB2[cg*8 + 2*q], sB2[cg*8 + 2*q + 1]);
            #pragma unroll 4
            for (int k = 0; k < 64; k++) {
                const ull* wp = reinterpret_cast<const ull*>(sW2 + k * 128 + cg * 8);
                ull wv[4];
                #pragma unroll
                for (int q = 0; q < 4; q++) wv[q] = wp[q];
                #pragma unroll
                for (int j = 0; j < 2; j++) {
                    float a = sH[(nl * 2 + j) * 65 + k];
                    ull ap = pack2(a, a);
                    #pragma unroll
                    for (int q = 0; q < 4; q++)
                        acc[j][q] = fma2(ap, wv[q], acc[j][q]);
                }
            }
            #pragma unroll
            for (int j = 0; j < 2; j++) {
                float* mp = sMid + (nl * 2 + j) * MSTR + cg * 8;
                #pragma unroll
                for (int q = 0; q < 4; q++) {
                    float2 v = unpack2(acc[j][q]);
                    v.x = fmaxf(v.x, 0.f); v.y = fmaxf(v.y, 0.f);
                    *(float2*)(mp + 2*q) = v;
                }
            }
        }
        __syncthreads();

        // ---- phase 2: 128 -> 64, *dinv, half2 out. TPN=8, NL=32, MPT=1.
        {
            int cg = tid % 8, nl = tid / 8;
            int node = base + nl;
            ull acc[4] = {0, 0, 0, 0};
            const float* mrow = sMid + nl * MSTR;
            #pragma unroll 4
            for (int k = 0; k < 128; k++) {
                const ull* wp = reinterpret_cast<const ull*>(sW3 + k * 64 + cg * 8);
                float a = mrow[k];
                ull ap = pack2(a, a);
                #pragma unroll
                for (int q = 0; q < 4; q++)
                    acc[q] = fma2(ap, wp[q], acc[q]);
            }
            if (node < N_NODES) {
                float dv = g_dinv[node];
                #pragma unroll
                for (int q = 0; q < 4; q++) {
                    float2 v = unpack2(acc[q]);
                    g_hbuf[(size_t)node * 32 + cg * 4 + q] =
                        __floats2half2_rn(v.x * dv, v.y * dv);
                }
            }
        }
    }
}

// ---------------------------------------------------------------- pooling + MLP

__global__ void pool_kernel(const void* __restrict__ batch) {
    int w = (blockIdx.x * blockDim.x + threadIdx.x) >> 5;
    int lane = threadIdx.x & 31;
    const int NPW = 64;
    int start = w * NPW;
    if (start >= N_NODES) return;
    int end = min(start + NPW, N_NODES);
    int is64 = g_is64;
    int c = lane * 2;
    float ax = 0.f, ay = 0.f;
    int curg = -1, cnt = 0;
    for (int i = start; i < end; i++) {
        int g = is64 ? (int)((const long long*)batch)[i] : ((const int*)batch)[i];
        if (g != curg) {
            if (curg >= 0) {
                atomicAdd(&g_psum[curg * 64 + c],     ax);
                atomicAdd(&g_psum[curg * 64 + c + 1], ay);
                if (lane == 0) atomicAdd(&g_pcnt[curg], cnt);
            }
            curg = g; ax = 0.f; ay = 0.f; cnt = 0;
        }
        float2 v = *(const float2*)(g_bufA + (size_t)i * 64 + c);
        ax += v.x; ay += v.y; cnt++;
    }
    if (curg >= 0) {
        atomicAdd(&g_psum[curg * 64 + c],     ax);
        atomicAdd(&g_psum[curg * 64 + c + 1], ay);
        if (lane == 0) atomicAdd(&g_pcnt[curg], cnt);
    }
}

__global__ void mlp_kernel(const float* __restrict__ Wl1, const float* __restrict__ bl1,
                           const float* __restrict__ Wl2, const float* __restrict__ bl2,
                           float* __restrict__ out) {
    __shared__ float sW1[64 * 32];
    __shared__ float sb1[32];
    __shared__ float sW2[32];
    __shared__ float sb2;
    int tid = threadIdx.x;
    for (int i = tid; i < 64 * 32; i += 256) sW1[i] = Wl1[i];
    if (tid < 32) { sb1[tid] = bl1[tid]; sW2[tid] = Wl2[tid]; }
    if (tid == 0) sb2 = bl2[0];
    __syncthreads();
    float inv = 1.0f / fmaxf((float)g_pcnt[tid], 1.0f);
    float hid[32];
    #pragma unroll
    for (int cc = 0; cc < 32; cc++) hid[cc] = sb1[cc];
    for (int k = 0; k < 64; k++) {
        float a = g_psum[tid * 64 + k] * inv;
        #pragma unroll
        for (int cc = 0; cc < 32; cc++) hid[cc] = fmaf(a, sW1[k * 32 + cc], hid[cc]);
    }
    float o = sb2;
    #pragma unroll
    for (int cc = 0; cc < 32; cc++) o = fmaf(fmaxf(hid[cc], 0.f), sW2[cc], o);
    out[tid] = o;
}

// ---------------------------------------------------------------- launch

extern "C" void kernel_launch(void* const* d_in, const int* in_sizes, int n_in,
                              void* d_out, int out_size) {
    const float* x    = (const float*)d_in[0];
    const void*  eidx = d_in[1];
    const void*  batch= d_in[2];
    const float* W1   = (const float*)d_in[3];
    const float* b1   = (const float*)d_in[4];
    const float* W2   = (const float*)d_in[5];
    const float* b2   = (const float*)d_in[6];
    const float* W3   = (const float*)d_in[7];
    const float* b3   = (const float*)d_in[8];
    const float* Wl1  = (const float*)d_in[9];
    const float* bl1  = (const float*)d_in[10];
    const float* Wl2  = (const float*)d_in[11];
    const float* bl2  = (const float*)d_in[12];
    float* out = (float*)d_out;

    // gemm23 smem: W2 + W3 + b2 + sH + sMid (floats) = ~90KB -> 2 blocks/SM
    constexpr int SM23 = (64*128 + 128*64 + 128 + 32*65 + 32*130) * 4;
    cudaFuncSetAttribute(gemm23_kernel,
                         cudaFuncAttributeMaxDynamicSharedMemorySize, SM23);

    const int warpGrid = (N_NODES * 32 + 255) / 256;
    const int GRID23 = 296;   // 2 blocks/SM x 148 SMs; weights staged once each

    zero_detect_kernel<<<(N_NODES + 255) / 256, 256>>>((const int*)eidx);
    hist_rank_kernel  <<<(N_EDGES + 255) / 256, 256>>>(eidx);
    scanfuse_kernel   <<<SCAN_BLOCKS, SCAN_CHUNK>>>(x);
    fill_kernel       <<<(N_EDGES + 255) / 256, 256>>>(eidx);

    // Layer 1 (fused): agg xs (8-d) + GEMM 8->64 + b1 + relu + dinv -> hbuf (fp16)
    aggX_gemm1_kernel<<<warpGrid, 256>>>(W1, b1);
    // Layer 2 agg: hbuf -> bufB (fp32, 64-d)
    agg64h_kernel<false><<<warpGrid, 256>>>(1, nullptr);
    // Fused GEMM2+GEMM3 (grid-stride): bufB -> relu 128-d (smem) -> *dinv -> hbuf
    gemm23_kernel<<<GRID23, 256, SM23>>>(W2, b2, W3);
    // Layer 3 agg: hbuf -> bufA (+b3, relu)
    agg64h_kernel<true><<<warpGrid, 256>>>(0, b3);

    pool_kernel<<<(((N_NODES + 63) / 64) * 32 + 255) / 256, 256>>>(batch);
    mlp_kernel<<<1, 256>>>(Wl1, bl1, Wl2, bl2, out);
}

// round 17
// speedup vs baseline: 1.2237x; 1.1448x over previous
#include <cuda_runtime.h>
#include <cuda_fp16.h>

#define N_NODES  100000
#define N_EDGES  3200000
#define N_GRAPHS 256

static __device__ int   g_is64;
static __device__ int   g_ssrc[N_EDGES];      // src sorted by dst (CSR payload)
static __device__ int   g_erank[N_EDGES];     // rank of edge within its dst bucket
static __device__ int   g_cnt[N_NODES];
static __device__ int   g_rowptr[N_NODES + 1];
static __device__ float g_dinv[N_NODES];
static __device__ __align__(16) float   g_xs[(size_t)N_NODES * 8];    // x * dinv
static __device__ __align__(16) float   g_bufA[(size_t)N_NODES * 128];
static __device__ __align__(16) float   g_bufB[(size_t)N_NODES * 64];
static __device__ __align__(16) __half2 g_hbuf[(size_t)N_NODES * 32]; // agg-only features
static __device__ float g_psum[N_GRAPHS * 64];
static __device__ int   g_pcnt[N_GRAPHS];
static __device__ unsigned long long g_scanstate[128];  // lookback: flag<<32 | value

static constexpr int SCAN_CHUNK  = 1024;
static constexpr int SCAN_BLOCKS = (N_NODES + SCAN_CHUNK - 1) / SCAN_CHUNK;

// ------------------------------------------------------------- f32x2 helpers

typedef unsigned long long ull;

__device__ __forceinline__ ull pack2(float x, float y) {
    ull r; asm("mov.b64 %0, {%1,%2};" : "=l"(r) : "f"(x), "f"(y)); return r;
}
__device__ __forceinline__ float2 unpack2(ull v) {
    float x, y; asm("mov.b64 {%0,%1}, %2;" : "=f"(x), "=f"(y) : "l"(v));
    return make_float2(x, y);
}
__device__ __forceinline__ ull fma2(ull a, ull b, ull c) {
    ull d; asm("fma.rn.f32x2 %0, %1, %2, %3;" : "=l"(d) : "l"(a), "l"(b), "l"(c));
    return d;
}

// ---------------------------------------------------------------- utilities

__global__ void zero_detect_kernel(const int* __restrict__ ei32) {
    int i = blockIdx.x * blockDim.x + threadIdx.x;
    if (i < N_NODES)      g_cnt[i]  = 0;
    if (i < N_GRAPHS*64)  g_psum[i] = 0.f;
    if (i < N_GRAPHS)     g_pcnt[i] = 0;
    if (i < 128)          g_scanstate[i] = 0ULL;
    if (i == 0) {
        // int64 tensors have the high int32 word zero for values < 2^31
        int allz = 1;
        for (int k = 1; k < 256; k += 2) allz &= (ei32[k] == 0);
        g_is64 = allz;
    }
}

// Degree histogram over dst; ALSO records each edge's rank within its dst
// bucket (the atomicAdd return), so the later scatter needs no atomics.
__global__ void hist_rank_kernel(const void* __restrict__ eidx) {
    int e = blockIdx.x * blockDim.x + threadIdx.x;
    if (e >= N_EDGES) return;
    int d;
    if (g_is64) d = (int)((const long long*)eidx)[(size_t)N_EDGES + e];
    else        d = ((const int*)eidx)[N_EDGES + e];
    g_erank[e] = atomicAdd(&g_cnt[d], 1);
}

// --------------------------------------------- single-pass scan (+ finalize)
//
// Decoupled-lookback exclusive scan of g_cnt -> g_rowptr, fused with dinv
// computation and x pre-scaling (xs = x * dinv). All SCAN_BLOCKS (98) blocks
// are co-resident on 148 SMs, so the spin lookback cannot deadlock.
__global__ void scanfuse_kernel(const float* __restrict__ x) {
    __shared__ int s[SCAN_CHUNK];
    __shared__ int sprefix;
    int tid = threadIdx.x, b = blockIdx.x;
    int i = b * SCAN_CHUNK + tid;
    int v = (i < N_NODES) ? g_cnt[i] : 0;
    s[tid] = v;
    __syncthreads();
    for (int off = 1; off < SCAN_CHUNK; off <<= 1) {
        int t = (tid >= off) ? s[tid - off] : 0;
        __syncthreads();
        s[tid] += t;
        __syncthreads();
    }
    int total = s[SCAN_CHUNK - 1];
    if (tid == 0) {
        if (b == 0) {
            atomicExch(&g_scanstate[0], (2ULL << 32) | (unsigned)total);
            sprefix = 0;
        } else {
            atomicExch(&g_scanstate[b], (1ULL << 32) | (unsigned)total);
            long long prefix = 0;
            int j = b - 1;
            while (true) {
                ull w;
                do { w = atomicAdd(&g_scanstate[j], 0ULL); } while ((w >> 32) == 0ULL);
                prefix += (unsigned)w;
                if ((w >> 32) == 2ULL) break;
                j--;
            }
            atomicExch(&g_scanstate[b], (2ULL << 32) | (unsigned)(prefix + total));
            sprefix = (int)prefix;
        }
    }
    __syncthreads();
    int pre = sprefix;
    if (i < N_NODES) {
        g_rowptr[i] = pre + s[tid] - v;   // exclusive
        float dv = rsqrtf((float)v + 1.0f);
        g_dinv[i] = dv;
        const float4* xp = (const float4*)(x + (size_t)i * 8);
        float4 u = xp[0], v4 = xp[1];
        float4* op = (float4*)(g_xs + (size_t)i * 8);
        op[0] = make_float4(u.x * dv, u.y * dv, u.z * dv, u.w * dv);
        op[1] = make_float4(v4.x * dv, v4.y * dv, v4.z * dv, v4.w * dv);
    }
    if (i == N_NODES) g_rowptr[N_NODES] = N_EDGES;
}

// Atomic-free scatter into CSR: slot = rowptr[dst] + precomputed rank.
__global__ void fill_kernel(const void* __restrict__ eidx) {
    int e = blockIdx.x * blockDim.x + threadIdx.x;
    if (e >= N_EDGES) return;
    int s, d;
    if (g_is64) {
        const long long* p = (const long long*)eidx;
        s = (int)p[e];
        d = (int)p[(size_t)N_EDGES + e];
    } else {
        const int* p = (const int*)eidx;
        s = p[e];
        d = p[N_EDGES + e];
    }
    g_ssrc[g_rowptr[d] + g_erank[e]] = s;
}

// ------------------------------------------------- layer 1: fused agg + GEMM
//
// With h' = dinv*h pre-scaled, GCN aggregation is out_i = dinv_i*(h'_i + sum h'_j).
// One warp per node: gather-sum xs (8-d), butterfly-reduce (full sum in every
// lane), each lane computes 2 cols of the 8->64 GEMM + bias + relu + dinv
// pre-scale, stored as half2 (consumed only by the layer-2 aggregation).
__global__ void aggX_gemm1_kernel(const float* __restrict__ W1,
                                  const float* __restrict__ b1) {
    __shared__ float sW[8 * 64];
    __shared__ float sB[64];
    int tid = threadIdx.x;
    for (int i = tid; i < 512; i += 256) sW[i] = W1[i];
    if (tid < 64) sB[tid] = b1[tid];
    __syncthreads();

    int w = (blockIdx.x * blockDim.x + tid) >> 5;
    if (w >= N_NODES) return;
    int lane = tid & 31;
    int beg = g_rowptr[w], end = g_rowptr[w + 1];
    float a0=0,a1=0,a2=0,a3=0,a4=0,a5=0,a6=0,a7=0;
    for (int e = beg + lane; e < end; e += 32) {
        int s = g_ssrc[e];
        const float4* xp = (const float4*)(g_xs + (size_t)s * 8);
        float4 u = xp[0], v = xp[1];
        a0 += u.x; a1 += u.y; a2 += u.z; a3 += u.w;
        a4 += v.x; a5 += v.y; a6 += v.z; a7 += v.w;
    }
    #pragma unroll
    for (int off = 16; off; off >>= 1) {
        a0 += __shfl_xor_sync(0xffffffffu, a0, off);
        a1 += __shfl_xor_sync(0xffffffffu, a1, off);
        a2 += __shfl_xor_sync(0xffffffffu, a2, off);
        a3 += __shfl_xor_sync(0xffffffffu, a3, off);
        a4 += __shfl_xor_sync(0xffffffffu, a4, off);
        a5 += __shfl_xor_sync(0xffffffffu, a5, off);
        a6 += __shfl_xor_sync(0xffffffffu, a6, off);
        a7 += __shfl_xor_sync(0xffffffffu, a7, off);
    }
    float dv = g_dinv[w];
    const float4* xp = (const float4*)(g_xs + (size_t)w * 8);
    float4 u = xp[0], v = xp[1];
    float s[8];
    s[0]=dv*(a0+u.x); s[1]=dv*(a1+u.y); s[2]=dv*(a2+u.z); s[3]=dv*(a3+u.w);
    s[4]=dv*(a4+v.x); s[5]=dv*(a5+v.y); s[6]=dv*(a6+v.z); s[7]=dv*(a7+v.w);
    int c = lane * 2;
    float o0 = sB[c], o1 = sB[c + 1];
    #pragma unroll
    for (int k = 0; k < 8; k++) {
        float2 wv = *(const float2*)&sW[k * 64 + c];
        o0 = fmaf(s[k], wv.x, o0);
        o1 = fmaf(s[k], wv.y, o1);
    }
    o0 = fmaxf(o0, 0.f) * dv;
    o1 = fmaxf(o1, 0.f) * dv;
    g_hbuf[(size_t)w * 32 + lane] = __floats2half2_rn(o0, o1);
}

// ---------------------------------------------------------------- aggregation

// F=64 aggregation from the half2 feature buffer. One warp per dst node, lane
// owns one half2 column pair; fp32 accumulation; 8-way edge unroll for MLP.
// outSel: 0 -> g_bufA, 1 -> g_bufB (resolved in-kernel).
template <bool BIAS_RELU>
__global__ void agg64h_kernel(int outSel, const float* __restrict__ bias) {
    int w = (blockIdx.x * blockDim.x + threadIdx.x) >> 5;
    if (w >= N_NODES) return;
    int lane = threadIdx.x & 31;
    float* __restrict__ out = outSel ? g_bufB : g_bufA;
    const __half2* __restrict__ in = g_hbuf;
    int e = g_rowptr[w], end = g_rowptr[w + 1];
    float ax0=0, ay0=0, ax1=0, ay1=0, ax2=0, ay2=0, ax3=0, ay3=0;
    for (; e + 8 <= end; e += 8) {
        int s0 = g_ssrc[e+0], s1 = g_ssrc[e+1], s2 = g_ssrc[e+2], s3 = g_ssrc[e+3];
        int s4 = g_ssrc[e+4], s5 = g_ssrc[e+5], s6 = g_ssrc[e+6], s7 = g_ssrc[e+7];
        __half2 h0 = in[(size_t)s0*32 + lane];
        __half2 h1 = in[(size_t)s1*32 + lane];
        __half2 h2 = in[(size_t)s2*32 + lane];
        __half2 h3 = in[(size_t)s3*32 + lane];
        __half2 h4 = in[(size_t)s4*32 + lane];
        __half2 h5 = in[(size_t)s5*32 + lane];
        __half2 h6 = in[(size_t)s6*32 + lane];
        __half2 h7 = in[(size_t)s7*32 + lane];
        float2 f0 = __half22float2(h0), f1 = __half22float2(h1);
        float2 f2 = __half22float2(h2), f3 = __half22float2(h3);
        float2 f4 = __half22float2(h4), f5 = __half22float2(h5);
        float2 f6 = __half22float2(h6), f7 = __half22float2(h7);
        ax0 += f0.x; ay0 += f0.y;  ax1 += f1.x; ay1 += f1.y;
        ax2 += f2.x; ay2 += f2.y;  ax3 += f3.x; ay3 += f3.y;
        ax0 += f4.x; ay0 += f4.y;  ax1 += f5.x; ay1 += f5.y;
        ax2 += f6.x; ay2 += f6.y;  ax3 += f7.x; ay3 += f7.y;
    }
    for (; e < end; e++) {
        int s = g_ssrc[e];
        float2 f = __half22float2(in[(size_t)s*32 + lane]);
        ax0 += f.x; ay0 += f.y;
    }
    float dv = g_dinv[w];
    float2 sv = __half22float2(in[(size_t)w*32 + lane]);
    float ox = dv * ((ax0 + ax1) + (ax2 + ax3) + sv.x);
    float oy = dv * ((ay0 + ay1) + (ay2 + ay3) + sv.y);
    int c = lane * 2;
    if (BIAS_RELU) {
        ox = fmaxf(ox + bias[c],     0.f);
        oy = fmaxf(oy + bias[c + 1], 0.f);
    }
    *(float2*)(out + (size_t)w*64 + c) = make_float2(ox, oy);
}

// ---------------------------------------------------------------- tiled GEMM
//
// Register-tiled node-parallel GEMM: each thread computes MPT nodes x CPT cols,
// amortizing the W smem stream MPT-fold, with fma.rn.f32x2 for 2x fp32 issue.
// inSel/outSel: 0 -> g_bufA, 1 -> g_bufB (in-kernel). OUTH: write half2 to g_hbuf.
// (Separate kernels for GEMM2/GEMM3 — the fused variant loses 2x occupancy and
// serializes phases behind __syncthreads; measured +90..130us in R14-R16.)
template <int IN, int OUT, int CPT, int MPT, bool ACT, bool SCALE, bool OUTH>
__global__ void gemm_tiled_kernel(int inSel, const float* __restrict__ W,
                                  const float* __restrict__ bias, int outSel) {
    constexpr int TPN = OUT / CPT;            // col-groups
    constexpr int NL  = 256 / TPN;            // node-lanes per block
    constexpr int NPB = NL * MPT;             // nodes per block
    constexpr int HP  = IN + 1;               // padded sH row (bank spread)
    extern __shared__ float smem[];
    float* sW = smem;                         // IN*OUT
    float* sH = smem + IN * OUT;              // NPB*HP
    float* sB = sH + NPB * HP;                // OUT
    const float* __restrict__ in_p  = inSel  ? g_bufB : g_bufA;
    float*       __restrict__ out_p = outSel ? g_bufB : g_bufA;
    int tid = threadIdx.x;
    for (int i = tid; i < IN * OUT; i += 256) sW[i] = W[i];
    for (int i = tid; i < OUT; i += 256) sB[i] = bias ? bias[i] : 0.f;
    int base = blockIdx.x * NPB;
    for (int i = tid; i < NPB * IN; i += 256) {
        int nd = i / IN, k = i % IN;
        int node = base + nd;
        sH[nd * HP + k] = (node < N_NODES) ? in_p[(size_t)node * IN + k] : 0.f;
    }
    __syncthreads();

    int cg = tid % TPN;                       // column group
    int nl = tid / TPN;                       // node lane
    ull acc[MPT][CPT / 2];
    #pragma unroll
    for (int j = 0; j < MPT; j++)
        #pragma unroll
        for (int q = 0; q < CPT / 2; q++)
            acc[j][q] = pack2(sB[cg*CPT + 2*q], sB[cg*CPT + 2*q + 1]);

    #pragma unroll 4
    for (int k = 0; k < IN; k++) {
        const ull* wp = reinterpret_cast<const ull*>(sW + k * OUT + cg * CPT);
        ull wv[CPT / 2];
        #pragma unroll
        for (int q = 0; q < CPT / 2; q++) wv[q] = wp[q];
        #pragma unroll
        for (int j = 0; j < MPT; j++) {
            float a = sH[(nl * MPT + j) * HP + k];
            ull ap = pack2(a, a);
            #pragma unroll
            for (int q = 0; q < CPT / 2; q++)
                acc[j][q] = fma2(ap, wv[q], acc[j][q]);
        }
    }

    #pragma unroll
    for (int j = 0; j < MPT; j++) {
        int node = base + nl * MPT + j;
        if (node >= N_NODES) continue;
        float dv = SCALE ? g_dinv[node] : 1.0f;
        #pragma unroll
        for (int q = 0; q < CPT / 2; q++) {
            float2 v = unpack2(acc[j][q]);
            if (ACT) { v.x = fmaxf(v.x, 0.f); v.y = fmaxf(v.y, 0.f); }
            if (SCALE) { v.x *= dv; v.y *= dv; }
            if (OUTH) {
                g_hbuf[(size_t)node * 32 + (cg * CPT) / 2 + q] =
                    __floats2half2_rn(v.x, v.y);
            } else {
                *(float2*)(out_p + (size_t)node * OUT + cg * CPT + 2*q) = v;
            }
        }
    }
}

// ---------------------------------------------------------------- pooling + MLP

__global__ void pool_kernel(const void* __restrict__ batch) {
    int w = (blockIdx.x * blockDim.x + threadIdx.x) >> 5;
    int lane = threadIdx.x & 31;
    const int NPW = 64;
    int start = w * NPW;
    if (start >= N_NODES) return;
    int end = min(start + NPW, N_NODES);
    int is64 = g_is64;
    int c = lane * 2;
    float ax = 0.f, ay = 0.f;
    int curg = -1, cnt = 0;
    for (int i = start; i < end; i++) {
        int g = is64 ? (int)((const long long*)batch)[i] : ((const int*)batch)[i];
        if (g != curg) {
            if (curg >= 0) {
                atomicAdd(&g_psum[curg * 64 + c],     ax);
                atomicAdd(&g_psum[curg * 64 + c + 1], ay);
                if (lane == 0) atomicAdd(&g_pcnt[curg], cnt);
            }
            curg = g; ax = 0.f; ay = 0.f; cnt = 0;
        }
        float2 v = *(const float2*)(g_bufA + (size_t)i * 64 + c);
        ax += v.x; ay += v.y; cnt++;
    }
    if (curg >= 0) {
        atomicAdd(&g_psum[curg * 64 + c],     ax);
        atomicAdd(&g_psum[curg * 64 + c + 1], ay);
        if (lane == 0) atomicAdd(&g_pcnt[curg], cnt);
    }
}

__global__ void mlp_kernel(const float* __restrict__ Wl1, const float* __restrict__ bl1,
                           const float* __restrict__ Wl2, const float* __restrict__ bl2,
                           float* __restrict__ out) {
    __shared__ float sW1[64 * 32];
    __shared__ float sb1[32];
    __shared__ float sW2[32];
    __shared__ float sb2;
    int tid = threadIdx.x;
    for (int i = tid; i < 64 * 32; i += 256) sW1[i] = Wl1[i];
    if (tid < 32) { sb1[tid] = bl1[tid]; sW2[tid] = Wl2[tid]; }
    if (tid == 0) sb2 = bl2[0];
    __syncthreads();
    float inv = 1.0f / fmaxf((float)g_pcnt[tid], 1.0f);
    float hid[32];
    #pragma unroll
    for (int cc = 0; cc < 32; cc++) hid[cc] = sb1[cc];
    for (int k = 0; k < 64; k++) {
        float a = g_psum[tid * 64 + k] * inv;
        #pragma unroll
        for (int cc = 0; cc < 32; cc++) hid[cc] = fmaf(a, sW1[k * 32 + cc], hid[cc]);
    }
    float o = sb2;
    #pragma unroll
    for (int cc = 0; cc < 32; cc++) o = fmaf(fmaxf(hid[cc], 0.f), sW2[cc], o);
    out[tid] = o;
}

// ---------------------------------------------------------------- launch

extern "C" void kernel_launch(void* const* d_in, const int* in_sizes, int n_in,
                              void* d_out, int out_size) {
    const float* x    = (const float*)d_in[0];
    const void*  eidx = d_in[1];
    const void*  batch= d_in[2];
    const float* W1   = (const float*)d_in[3];
    const float* b1   = (const float*)d_in[4];
    const float* W2   = (const float*)d_in[5];
    const float* b2   = (const float*)d_in[6];
    const float* W3   = (const float*)d_in[7];
    const float* b3   = (const float*)d_in[8];
    const float* Wl1  = (const float*)d_in[9];
    const float* bl1  = (const float*)d_in[10];
    const float* Wl2  = (const float*)d_in[11];
    const float* bl2  = (const float*)d_in[12];
    float* out = (float*)d_out;

    // gemm2: 64->128, CPT=8, MPT=4 -> NPB=64. smem = 64*128 + 64*65 + 128 floats
    constexpr int SM2 = (64*128 + 64*65 + 128) * 4;
    // gemm3: 128->64, CPT=8, MPT=2 -> NPB=64. smem = 128*64 + 64*129 + 64 floats
    constexpr int SM3 = (128*64 + 64*129 + 64) * 4;
    cudaFuncSetAttribute(gemm_tiled_kernel<64,128,8,4,true,false,false>,
                         cudaFuncAttributeMaxDynamicSharedMemorySize, SM2);
    cudaFuncSetAttribute(gemm_tiled_kernel<128,64,8,2,false,true,true>,
                         cudaFuncAttributeMaxDynamicSharedMemorySize, SM3);

    const int warpGrid = (N_NODES * 32 + 255) / 256;
    const int tileGrid = (N_NODES + 63) / 64;

    zero_detect_kernel<<<(N_NODES + 255) / 256, 256>>>((const int*)eidx);
    hist_rank_kernel  <<<(N_EDGES + 255) / 256, 256>>>(eidx);
    scanfuse_kernel   <<<SCAN_BLOCKS, SCAN_CHUNK>>>(x);
    fill_kernel       <<<(N_EDGES + 255) / 256, 256>>>(eidx);

    // Layer 1 (fused): agg xs (8-d) + GEMM 8->64 + b1 + relu + dinv -> hbuf (fp16)
    aggX_gemm1_kernel<<<warpGrid, 256>>>(W1, b1);
    // Layer 2: aggregate (hbuf -> bufB fp32), GEMM 64->128 + b2 + relu (bufB -> bufA)
    agg64h_kernel<false><<<warpGrid, 256>>>(1, nullptr);
    gemm_tiled_kernel<64,128,8,4,true,false,false><<<tileGrid, 256, SM2>>>(1, W2, b2, 0);
    // Layer 3: GEMM 128->64 * dinv (bufA -> hbuf fp16), aggregate + b3 + relu (-> bufA)
    gemm_tiled_kernel<128,64,8,2,false,true,true><<<tileGrid, 256, SM3>>>(0, W3, nullptr, 0);
    // Layer 3 agg: hbuf -> bufA (+b3, relu)
    agg64h_kernel<true><<<warpGrid, 256>>>(0, b3);

    pool_kernel<<<(((N_NODES + 63) / 64) * 32 + 255) / 256, 256>>>(batch);
    mlp_kernel<<<1, 256>>>(Wl1, bl1, Wl2, bl2, out);
}